// round 15
// baseline (speedup 1.0000x reference)
#include <cuda_runtime.h>
#include <cuda_bf16.h>
#include <cuda_fp16.h>
#include <cstdint>

#define NN    100000
#define EE    1600000
#define INC   256
#define OUTC  128

// ------------------------- device scratch -------------------------
__device__ __half g_Hh[(size_t)NN * OUTC];    // H = X @ W^T (fp16)
__device__ int    g_row_ptr[NN + 1];
__device__ __half g_Wh[OUTC * INC];           // W in fp16

// ------------------------- helpers -------------------------
__device__ __forceinline__ uint32_t smem_u32(const void* p) {
    uint32_t a;
    asm("{ .reg .u64 t; cvta.to.shared.u64 t, %1; cvt.u32.u64 %0, t; }"
        : "=r"(a) : "l"(p));
    return a;
}
__device__ __forceinline__ void ldm_x4(uint32_t* r, uint32_t addr) {
    asm volatile("ldmatrix.sync.aligned.m8n8.x4.shared.b16 {%0,%1,%2,%3}, [%4];"
                 : "=r"(r[0]), "=r"(r[1]), "=r"(r[2]), "=r"(r[3]) : "r"(addr));
}
__device__ __forceinline__ void mma_fp16(float* c, const uint32_t* a, const uint32_t* b) {
    asm volatile(
        "mma.sync.aligned.m16n8k16.row.col.f32.f16.f16.f32 "
        "{%0,%1,%2,%3}, {%4,%5,%6,%7}, {%8,%9}, {%0,%1,%2,%3};"
        : "+f"(c[0]), "+f"(c[1]), "+f"(c[2]), "+f"(c[3])
        : "r"(a[0]), "r"(a[1]), "r"(a[2]), "r"(a[3]), "r"(b[0]), "r"(b[1]));
}

// ------------------------- Kernel 0: fused prep (W->fp16 + row_ptr) -----------------
__global__ void prep_kernel(const float* __restrict__ W,
                            const int*   __restrict__ A_rows)
{
    int i = blockIdx.x * blockDim.x + threadIdx.x;
    if (i < OUTC * INC)
        g_Wh[i] = __float2half_rn(W[i]);
    if (i <= NN) {
        int lo = 0, hi = EE;
        while (lo < hi) {
            int mid = (lo + hi) >> 1;
            if (A_rows[mid] < i) lo = mid + 1;
            else                 hi = mid;
        }
        g_row_ptr[i] = lo;
    }
}

// ------------------------- Kernel 1: fp16 mma.sync GEMM, K-tile 128 -----------------
// CTA tile 128x128, 2 K-tiles of 128. 8 warps (256 thr): warp tile 32 rows x 64 cols.
// SMEM (halves, row stride LDH=136, conflict-free ldmatrix): A[128][136], B[128][136]
#define LDH 136
#define SM_A 0
#define SM_B (128 * LDH)
#define SM_HALVES (2 * 128 * LDH)
#define SM_BYTES (SM_HALVES * 2)   // 69632

__global__ __launch_bounds__(256, 2)
void gemm_tc_kernel(const float* __restrict__ X)
{
    extern __shared__ __half sm[];
    const uint32_t sb = smem_u32(sm);

    const int tid = threadIdx.x;
    const int wid = tid >> 5;
    const int lane = tid & 31;
    const int block_row = blockIdx.x * 128;

    const int wm = (wid & 3) * 32;   // warp row offset
    const int wn = (wid >> 2) * 64;  // warp col offset

    float c[2][8][4];
#pragma unroll
    for (int mi = 0; mi < 2; mi++)
#pragma unroll
        for (int ni = 0; ni < 8; ni++)
#pragma unroll
            for (int j = 0; j < 4; j++)
                c[mi][ni][j] = 0.0f;

    const int a_row = (lane & 7) + 8 * ((lane >> 3) & 1);
    const int a_kh  = 8 * (lane >> 4);
    // B ldmatrix.x4 lane mapping for an ni-PAIR (16 n-rows x 2 k-halves)
    const int b_row = (lane & 7) + 8 * (lane >> 4);
    const int b_kh  = 8 * ((lane >> 3) & 1);

#pragma unroll 1
    for (int kt = 0; kt < 2; kt++) {
        const int k0 = kt * 128;
        if (kt) __syncthreads();

        // --- X tile: 128 rows x 128 floats -> fp16 (4096 float4 slots, 16/thread) ---
#pragma unroll
        for (int i = 0; i < 16; i++) {
            int slot = i * 256 + tid;
            int row  = slot >> 5;              // 32 float4 per row
            int kq   = (slot & 31) << 2;
            int gm   = block_row + row;
            float4 v = make_float4(0.f, 0.f, 0.f, 0.f);
            if (gm < NN)
                v = *reinterpret_cast<const float4*>(X + (size_t)gm * INC + k0 + kq);
            __half2 p0 = __floats2half2_rn(v.x, v.y);
            __half2 p1 = __floats2half2_rn(v.z, v.w);
            uint2 w;
            w.x = *reinterpret_cast<uint32_t*>(&p0);
            w.y = *reinterpret_cast<uint32_t*>(&p1);
            *reinterpret_cast<uint2*>(&sm[SM_A + row * LDH + kq]) = w;
        }
        // --- W tile: 128 n x 128 halves (2048 uint4 slots, 8/thread) ---
#pragma unroll
        for (int i = 0; i < 8; i++) {
            int slot = i * 256 + tid;
            int n    = slot >> 4;              // 16 uint4 slots per row
            int kc   = (slot & 15) << 3;
            *reinterpret_cast<uint4*>(&sm[SM_B + n * LDH + kc]) =
                *reinterpret_cast<const uint4*>(g_Wh + n * INC + k0 + kc);
        }
        __syncthreads();

        // --- compute: 8 k16 steps ---
#pragma unroll
        for (int ks = 0; ks < 8; ks++) {
            uint32_t a[2][4];
#pragma unroll
            for (int mi = 0; mi < 2; mi++) {
                int hoff = (wm + mi * 16 + a_row) * LDH + ks * 16 + a_kh;
                ldm_x4(a[mi], sb + 2 * (SM_A + hoff));
            }
#pragma unroll
            for (int p = 0; p < 4; p++) {      // ni pairs (2p, 2p+1)
                uint32_t bq[4];
                int hoff = (wn + p * 16 + b_row) * LDH + ks * 16 + b_kh;
                ldm_x4(bq, sb + 2 * (SM_B + hoff));
#pragma unroll
                for (int mi = 0; mi < 2; mi++) {
                    mma_fp16(c[mi][2 * p + 0], a[mi], bq + 0);
                    mma_fp16(c[mi][2 * p + 1], a[mi], bq + 2);
                }
            }
        }
    }

    // --- epilogue: write fp16 H ---
    const int r0 = (lane >> 2);
    const int cb = (lane & 3) * 2;
#pragma unroll
    for (int mi = 0; mi < 2; mi++) {
#pragma unroll
        for (int ni = 0; ni < 8; ni++) {
            int col = wn + ni * 8 + cb;
            int gm0 = block_row + wm + mi * 16 + r0;
            int gm1 = gm0 + 8;
            if (gm0 < NN)
                *reinterpret_cast<__half2*>(g_Hh + (size_t)gm0 * OUTC + col) =
                    __floats2half2_rn(c[mi][ni][0], c[mi][ni][1]);
            if (gm1 < NN)
                *reinterpret_cast<__half2*>(g_Hh + (size_t)gm1 * OUTC + col) =
                    __floats2half2_rn(c[mi][ni][2], c[mi][ni][3]);
        }
    }
}

// ------------------------- Kernel 3: CSR SpMM, warp per row (R14 proven) ------------
__global__ __launch_bounds__(256)
void spmm_kernel(const int*   __restrict__ A_cols,
                 const float* __restrict__ A_vals,
                 float*       __restrict__ out)
{
    const int lane = threadIdx.x & 31;
    const int r    = blockIdx.x * 8 + (threadIdx.x >> 5);
    if (r >= NN) return;                       // warp-uniform

    const int beg = g_row_ptr[r];
    const int end = g_row_ptr[r + 1];

    float4 acc = make_float4(0.f, 0.f, 0.f, 0.f);
    const __half* __restrict__ Hbase = g_Hh;

#pragma unroll 1
    for (int base = beg; base < end; base += 32) {
        int   e   = base + lane;
        int   col = 0;
        float v   = 0.f;
        if (e < end) { col = __ldg(A_cols + e); v = __ldg(A_vals + e); }
        const int cnt = min(32, end - base);

#pragma unroll 8
        for (int j = 0; j < cnt; j++) {
            int   cj = __shfl_sync(0xffffffffu, col, j);
            float vj = __shfl_sync(0xffffffffu, v,   j);
            uint2 hraw = *reinterpret_cast<const uint2*>(
                             Hbase + (size_t)cj * OUTC + lane * 4);
            __half2 h0 = *reinterpret_cast<__half2*>(&hraw.x);
            __half2 h1 = *reinterpret_cast<__half2*>(&hraw.y);
            float2 f0 = __half22float2(h0);
            float2 f1 = __half22float2(h1);
            acc.x = fmaf(vj, f0.x, acc.x);
            acc.y = fmaf(vj, f0.y, acc.y);
            acc.z = fmaf(vj, f1.x, acc.z);
            acc.w = fmaf(vj, f1.y, acc.w);
        }
    }

    *reinterpret_cast<float4*>(out + (size_t)r * OUTC + lane * 4) = acc;
}

// ---------------------------------------------------------------------------
extern "C" void kernel_launch(void* const* d_in, const int* in_sizes, int n_in,
                              void* d_out, int out_size)
{
    const float* X      = (const float*)d_in[0];   // [NN, INC]
    const float* W      = (const float*)d_in[1];   // [OUTC, INC]
    const int*   A_rows = (const int*)  d_in[2];   // [EE] sorted
    const int*   A_cols = (const int*)  d_in[3];   // [EE]
    const float* A_vals = (const float*)d_in[4];   // [EE]
    float*       out    = (float*)d_out;           // [NN, OUTC]

    cudaFuncSetAttribute(gemm_tc_kernel,
                         cudaFuncAttributeMaxDynamicSharedMemorySize, SM_BYTES);

    prep_kernel<<<(NN + 1 + 255) / 256, 256>>>(W, A_rows);
    gemm_tc_kernel<<<(NN + 127) / 128, 256, SM_BYTES>>>(X);
    spmm_kernel<<<(NN + 7) / 8, 256>>>(A_cols, A_vals, out);
}

// round 16
// speedup vs baseline: 1.0784x; 1.0784x over previous
#include <cuda_runtime.h>
#include <cuda_bf16.h>
#include <cuda_fp16.h>
#include <cstdint>

#define NN    100000
#define EE    1600000
#define INC   256
#define OUTC  128

// ------------------------- device scratch -------------------------
__device__ __half g_Hh[(size_t)NN * OUTC];    // H = X @ W^T (fp16)
__device__ int    g_row_ptr[NN + 1];
__device__ __half g_Wh[OUTC * INC];           // W in fp16

// ------------------------- helpers -------------------------
__device__ __forceinline__ uint32_t smem_u32(const void* p) {
    uint32_t a;
    asm("{ .reg .u64 t; cvta.to.shared.u64 t, %1; cvt.u32.u64 %0, t; }"
        : "=r"(a) : "l"(p));
    return a;
}
__device__ __forceinline__ void ldm_x4(uint32_t* r, uint32_t addr) {
    asm volatile("ldmatrix.sync.aligned.m8n8.x4.shared.b16 {%0,%1,%2,%3}, [%4];"
                 : "=r"(r[0]), "=r"(r[1]), "=r"(r[2]), "=r"(r[3]) : "r"(addr));
}
__device__ __forceinline__ void mma_fp16(float* c, const uint32_t* a, const uint32_t* b) {
    asm volatile(
        "mma.sync.aligned.m16n8k16.row.col.f32.f16.f16.f32 "
        "{%0,%1,%2,%3}, {%4,%5,%6,%7}, {%8,%9}, {%0,%1,%2,%3};"
        : "+f"(c[0]), "+f"(c[1]), "+f"(c[2]), "+f"(c[3])
        : "r"(a[0]), "r"(a[1]), "r"(a[2]), "r"(a[3]), "r"(b[0]), "r"(b[1]));
}

// ------------------------- Kernel 0: prep = W->fp16 + row_ptr scatter ---------------
// row_ptr[r] = lower_bound(A_rows, r). For each adjacent pair (A_rows[e], A_rows[e+1]]
// write e+1; thread 0 fills the prefix; last thread fills through NN.
// O(E) coalesced reads, no dependent-load chains.
__global__ void prep_kernel(const float* __restrict__ W,
                            const int*   __restrict__ A_rows)
{
    int e = blockIdx.x * blockDim.x + threadIdx.x;
    if (e < OUTC * INC)
        g_Wh[e] = __float2half_rn(W[e]);
    if (e >= EE) return;

    int cur = A_rows[e];
    if (e == 0) {
        for (int r = 0; r <= cur; r++) g_row_ptr[r] = 0;
    }
    int nxt = (e == EE - 1) ? NN : A_rows[e + 1];
    for (int r = cur + 1; r <= nxt; r++) g_row_ptr[r] = e + 1;
}

// ------------------------- Kernel 1: fp16 mma.sync GEMM (R11 proven shape) ----------
// CTA tile 128x128, K-tiles of 64. 8 warps (256 thr): warp tile 32 rows x 64 cols.
// SMEM (halves, row stride LDH=72): A[128][72], B[128][72]
#define LDH 72
#define SM_A 0
#define SM_B (128 * LDH)
#define SM_HALVES (2 * 128 * LDH)
#define SM_BYTES (SM_HALVES * 2)   // 36864

__global__ __launch_bounds__(256, 2)
void gemm_tc_kernel(const float* __restrict__ X)
{
    extern __shared__ __half sm[];
    const uint32_t sb = smem_u32(sm);

    const int tid = threadIdx.x;
    const int wid = tid >> 5;
    const int lane = tid & 31;
    const int block_row = blockIdx.x * 128;

    const int wm = (wid & 3) * 32;   // warp row offset
    const int wn = (wid >> 2) * 64;  // warp col offset

    float c[2][8][4];
#pragma unroll
    for (int mi = 0; mi < 2; mi++)
#pragma unroll
        for (int ni = 0; ni < 8; ni++)
#pragma unroll
            for (int j = 0; j < 4; j++)
                c[mi][ni][j] = 0.0f;

    const int a_row = (lane & 7) + 8 * ((lane >> 3) & 1);
    const int a_kh  = 8 * (lane >> 4);
    // B ldmatrix.x4 lane mapping for an ni-PAIR (16 n-rows x 2 k-halves)
    const int b_row = (lane & 7) + 8 * (lane >> 4);
    const int b_kh  = 8 * ((lane >> 3) & 1);

#pragma unroll 1
    for (int kt = 0; kt < 4; kt++) {
        const int k0 = kt * 64;
        if (kt) __syncthreads();

        // --- X tile: 128 rows x 64 floats -> fp16 (2048 float4 slots, 8/thread) ---
#pragma unroll
        for (int i = 0; i < 8; i++) {
            int slot = i * 256 + tid;
            int row  = slot >> 4;
            int kq   = (slot & 15) << 2;
            int gm   = block_row + row;
            float4 v = make_float4(0.f, 0.f, 0.f, 0.f);
            if (gm < NN)
                v = *reinterpret_cast<const float4*>(X + (size_t)gm * INC + k0 + kq);
            __half2 p0 = __floats2half2_rn(v.x, v.y);
            __half2 p1 = __floats2half2_rn(v.z, v.w);
            uint2 w;
            w.x = *reinterpret_cast<uint32_t*>(&p0);
            w.y = *reinterpret_cast<uint32_t*>(&p1);
            *reinterpret_cast<uint2*>(&sm[SM_A + row * LDH + kq]) = w;
        }
        // --- W tile: 128 n x 64 halves (1024 uint4 slots, 4/thread) ---
#pragma unroll
        for (int i = 0; i < 4; i++) {
            int slot = i * 256 + tid;
            int n    = slot >> 3;
            int kc   = (slot & 7) << 3;
            *reinterpret_cast<uint4*>(&sm[SM_B + n * LDH + kc]) =
                *reinterpret_cast<const uint4*>(g_Wh + n * INC + k0 + kc);
        }
        __syncthreads();

        // --- compute: 4 k16 steps ---
#pragma unroll
        for (int ks = 0; ks < 4; ks++) {
            uint32_t a[2][4];
#pragma unroll
            for (int mi = 0; mi < 2; mi++) {
                int hoff = (wm + mi * 16 + a_row) * LDH + ks * 16 + a_kh;
                ldm_x4(a[mi], sb + 2 * (SM_A + hoff));
            }
#pragma unroll
            for (int p = 0; p < 4; p++) {      // ni pairs (2p, 2p+1)
                uint32_t bq[4];
                int hoff = (wn + p * 16 + b_row) * LDH + ks * 16 + b_kh;
                ldm_x4(bq, sb + 2 * (SM_B + hoff));
#pragma unroll
                for (int mi = 0; mi < 2; mi++) {
                    mma_fp16(c[mi][2 * p + 0], a[mi], bq + 0);
                    mma_fp16(c[mi][2 * p + 1], a[mi], bq + 2);
                }
            }
        }
    }

    // --- epilogue: write fp16 H ---
    const int r0 = (lane >> 2);
    const int cb = (lane & 3) * 2;
#pragma unroll
    for (int mi = 0; mi < 2; mi++) {
#pragma unroll
        for (int ni = 0; ni < 8; ni++) {
            int col = wn + ni * 8 + cb;
            int gm0 = block_row + wm + mi * 16 + r0;
            int gm1 = gm0 + 8;
            if (gm0 < NN)
                *reinterpret_cast<__half2*>(g_Hh + (size_t)gm0 * OUTC + col) =
                    __floats2half2_rn(c[mi][ni][0], c[mi][ni][1]);
            if (gm1 < NN)
                *reinterpret_cast<__half2*>(g_Hh + (size_t)gm1 * OUTC + col) =
                    __floats2half2_rn(c[mi][ni][2], c[mi][ni][3]);
        }
    }
}

// ------------------------- Kernel 2: CSR SpMM, warp per row (R14 proven) ------------
__global__ __launch_bounds__(256)
void spmm_kernel(const int*   __restrict__ A_cols,
                 const float* __restrict__ A_vals,
                 float*       __restrict__ out)
{
    const int lane = threadIdx.x & 31;
    const int r    = blockIdx.x * 8 + (threadIdx.x >> 5);
    if (r >= NN) return;                       // warp-uniform

    const int beg = g_row_ptr[r];
    const int end = g_row_ptr[r + 1];

    float4 acc = make_float4(0.f, 0.f, 0.f, 0.f);
    const __half* __restrict__ Hbase = g_Hh;

#pragma unroll 1
    for (int base = beg; base < end; base += 32) {
        int   e   = base + lane;
        int   col = 0;
        float v   = 0.f;
        if (e < end) { col = __ldg(A_cols + e); v = __ldg(A_vals + e); }
        const int cnt = min(32, end - base);

#pragma unroll 8
        for (int j = 0; j < cnt; j++) {
            int   cj = __shfl_sync(0xffffffffu, col, j);
            float vj = __shfl_sync(0xffffffffu, v,   j);
            uint2 hraw = *reinterpret_cast<const uint2*>(
                             Hbase + (size_t)cj * OUTC + lane * 4);
            __half2 h0 = *reinterpret_cast<__half2*>(&hraw.x);
            __half2 h1 = *reinterpret_cast<__half2*>(&hraw.y);
            float2 f0 = __half22float2(h0);
            float2 f1 = __half22float2(h1);
            acc.x = fmaf(vj, f0.x, acc.x);
            acc.y = fmaf(vj, f0.y, acc.y);
            acc.z = fmaf(vj, f1.x, acc.z);
            acc.w = fmaf(vj, f1.y, acc.w);
        }
    }

    *reinterpret_cast<float4*>(out + (size_t)r * OUTC + lane * 4) = acc;
}

// ---------------------------------------------------------------------------
extern "C" void kernel_launch(void* const* d_in, const int* in_sizes, int n_in,
                              void* d_out, int out_size)
{
    const float* X      = (const float*)d_in[0];   // [NN, INC]
    const float* W      = (const float*)d_in[1];   // [OUTC, INC]
    const int*   A_rows = (const int*)  d_in[2];   // [EE] sorted
    const int*   A_cols = (const int*)  d_in[3];   // [EE]
    const float* A_vals = (const float*)d_in[4];   // [EE]
    float*       out    = (float*)d_out;           // [NN, OUTC]

    cudaFuncSetAttribute(gemm_tc_kernel,
                         cudaFuncAttributeMaxDynamicSharedMemorySize, SM_BYTES);

    prep_kernel<<<(EE + 255) / 256, 256>>>(W, A_rows);
    gemm_tc_kernel<<<(NN + 127) / 128, 256, SM_BYTES>>>(X);
    spmm_kernel<<<(NN + 7) / 8, 256>>>(A_cols, A_vals, out);
}

// round 17
// speedup vs baseline: 1.1185x; 1.0372x over previous
#include <cuda_runtime.h>
#include <cuda_bf16.h>
#include <cuda_fp16.h>
#include <cstdint>

#define NN    100000
#define EE    1600000
#define INC   256
#define OUTC  128

// ------------------------- device scratch -------------------------
__device__ __half g_Hh[(size_t)NN * OUTC];    // H = X @ W^T (fp16)
__device__ int    g_row_ptr[NN + 1];
__device__ __half g_Wh[OUTC * INC];           // W in fp16

// ------------------------- helpers -------------------------
__device__ __forceinline__ uint32_t smem_u32(const void* p) {
    uint32_t a;
    asm("{ .reg .u64 t; cvta.to.shared.u64 t, %1; cvt.u32.u64 %0, t; }"
        : "=r"(a) : "l"(p));
    return a;
}
__device__ __forceinline__ void ldm_x4(uint32_t* r, uint32_t addr) {
    asm volatile("ldmatrix.sync.aligned.m8n8.x4.shared.b16 {%0,%1,%2,%3}, [%4];"
                 : "=r"(r[0]), "=r"(r[1]), "=r"(r[2]), "=r"(r[3]) : "r"(addr));
}
__device__ __forceinline__ void mma_fp16(float* c, const uint32_t* a, const uint32_t* b) {
    asm volatile(
        "mma.sync.aligned.m16n8k16.row.col.f32.f16.f16.f32 "
        "{%0,%1,%2,%3}, {%4,%5,%6,%7}, {%8,%9}, {%0,%1,%2,%3};"
        : "+f"(c[0]), "+f"(c[1]), "+f"(c[2]), "+f"(c[3])
        : "r"(a[0]), "r"(a[1]), "r"(a[2]), "r"(a[3]), "r"(b[0]), "r"(b[1]));
}

// ------------------------- Kernel 0: prep = W->fp16 + row_ptr scatter (int4) --------
// row_ptr[r] = lower_bound(A_rows, r). Thread t owns edges [4t, 4t+4): writes the
// boundary runs after each of its 4 edges; thread 0 also fills the prefix.
__global__ void prep_kernel(const float* __restrict__ W,
                            const int*   __restrict__ A_rows)
{
    int t = blockIdx.x * blockDim.x + threadIdx.x;
    if (t < OUTC * INC)
        g_Wh[t] = __float2half_rn(W[t]);
    if (t >= EE / 4) return;

    const int e = t * 4;
    int4 r4 = *reinterpret_cast<const int4*>(A_rows + e);
    int nxt = (e + 4 < EE) ? __ldg(A_rows + e + 4) : NN;

    if (e == 0)
        for (int r = 0; r <= r4.x; r++) g_row_ptr[r] = 0;
    for (int r = r4.x + 1; r <= r4.y; r++) g_row_ptr[r] = e + 1;
    for (int r = r4.y + 1; r <= r4.z; r++) g_row_ptr[r] = e + 2;
    for (int r = r4.z + 1; r <= r4.w; r++) g_row_ptr[r] = e + 3;
    for (int r = r4.w + 1; r <= nxt;  r++) g_row_ptr[r] = e + 4;
}

// ------------------------- Kernel 1: fp16 mma.sync GEMM (R11 proven shape) ----------
// CTA tile 128x128, K-tiles of 64. 8 warps (256 thr): warp tile 32 rows x 64 cols.
// SMEM (halves, row stride LDH=72): A[128][72], B[128][72]
#define LDH 72
#define SM_A 0
#define SM_B (128 * LDH)
#define SM_HALVES (2 * 128 * LDH)
#define SM_BYTES (SM_HALVES * 2)   // 36864

__global__ __launch_bounds__(256, 2)
void gemm_tc_kernel(const float* __restrict__ X)
{
    extern __shared__ __half sm[];
    const uint32_t sb = smem_u32(sm);

    const int tid = threadIdx.x;
    const int wid = tid >> 5;
    const int lane = tid & 31;
    const int block_row = blockIdx.x * 128;

    const int wm = (wid & 3) * 32;   // warp row offset
    const int wn = (wid >> 2) * 64;  // warp col offset

    float c[2][8][4];
#pragma unroll
    for (int mi = 0; mi < 2; mi++)
#pragma unroll
        for (int ni = 0; ni < 8; ni++)
#pragma unroll
            for (int j = 0; j < 4; j++)
                c[mi][ni][j] = 0.0f;

    const int a_row = (lane & 7) + 8 * ((lane >> 3) & 1);
    const int a_kh  = 8 * (lane >> 4);
    // B ldmatrix.x4 lane mapping for an ni-PAIR (16 n-rows x 2 k-halves)
    const int b_row = (lane & 7) + 8 * (lane >> 4);
    const int b_kh  = 8 * ((lane >> 3) & 1);

#pragma unroll 1
    for (int kt = 0; kt < 4; kt++) {
        const int k0 = kt * 64;
        if (kt) __syncthreads();

        // --- X tile: 128 rows x 64 floats -> fp16 (2048 float4 slots, 8/thread) ---
#pragma unroll
        for (int i = 0; i < 8; i++) {
            int slot = i * 256 + tid;
            int row  = slot >> 4;
            int kq   = (slot & 15) << 2;
            int gm   = block_row + row;
            float4 v = make_float4(0.f, 0.f, 0.f, 0.f);
            if (gm < NN)
                v = *reinterpret_cast<const float4*>(X + (size_t)gm * INC + k0 + kq);
            __half2 p0 = __floats2half2_rn(v.x, v.y);
            __half2 p1 = __floats2half2_rn(v.z, v.w);
            uint2 w;
            w.x = *reinterpret_cast<uint32_t*>(&p0);
            w.y = *reinterpret_cast<uint32_t*>(&p1);
            *reinterpret_cast<uint2*>(&sm[SM_A + row * LDH + kq]) = w;
        }
        // --- W tile: 128 n x 64 halves (1024 uint4 slots, 4/thread) ---
#pragma unroll
        for (int i = 0; i < 4; i++) {
            int slot = i * 256 + tid;
            int n    = slot >> 3;
            int kc   = (slot & 7) << 3;
            *reinterpret_cast<uint4*>(&sm[SM_B + n * LDH + kc]) =
                *reinterpret_cast<const uint4*>(g_Wh + n * INC + k0 + kc);
        }
        __syncthreads();

        // --- compute: 4 k16 steps ---
#pragma unroll
        for (int ks = 0; ks < 4; ks++) {
            uint32_t a[2][4];
#pragma unroll
            for (int mi = 0; mi < 2; mi++) {
                int hoff = (wm + mi * 16 + a_row) * LDH + ks * 16 + a_kh;
                ldm_x4(a[mi], sb + 2 * (SM_A + hoff));
            }
#pragma unroll
            for (int p = 0; p < 4; p++) {      // ni pairs (2p, 2p+1)
                uint32_t bq[4];
                int hoff = (wn + p * 16 + b_row) * LDH + ks * 16 + b_kh;
                ldm_x4(bq, sb + 2 * (SM_B + hoff));
#pragma unroll
                for (int mi = 0; mi < 2; mi++) {
                    mma_fp16(c[mi][2 * p + 0], a[mi], bq + 0);
                    mma_fp16(c[mi][2 * p + 1], a[mi], bq + 2);
                }
            }
        }
    }

    // --- epilogue: write fp16 H ---
    const int r0 = (lane >> 2);
    const int cb = (lane & 3) * 2;
#pragma unroll
    for (int mi = 0; mi < 2; mi++) {
#pragma unroll
        for (int ni = 0; ni < 8; ni++) {
            int col = wn + ni * 8 + cb;
            int gm0 = block_row + wm + mi * 16 + r0;
            int gm1 = gm0 + 8;
            if (gm0 < NN)
                *reinterpret_cast<__half2*>(g_Hh + (size_t)gm0 * OUTC + col) =
                    __floats2half2_rn(c[mi][ni][0], c[mi][ni][1]);
            if (gm1 < NN)
                *reinterpret_cast<__half2*>(g_Hh + (size_t)gm1 * OUTC + col) =
                    __floats2half2_rn(c[mi][ni][2], c[mi][ni][3]);
        }
    }
}

// ------------------------- Kernel 2: CSR SpMM, warp per row (R14 proven) ------------
__global__ __launch_bounds__(256)
void spmm_kernel(const int*   __restrict__ A_cols,
                 const float* __restrict__ A_vals,
                 float*       __restrict__ out)
{
    const int lane = threadIdx.x & 31;
    const int r    = blockIdx.x * 8 + (threadIdx.x >> 5);
    if (r >= NN) return;                       // warp-uniform

    const int beg = g_row_ptr[r];
    const int end = g_row_ptr[r + 1];

    float4 acc = make_float4(0.f, 0.f, 0.f, 0.f);
    const __half* __restrict__ Hbase = g_Hh;

#pragma unroll 1
    for (int base = beg; base < end; base += 32) {
        int   e   = base + lane;
        int   col = 0;
        float v   = 0.f;
        if (e < end) { col = __ldg(A_cols + e); v = __ldg(A_vals + e); }
        const int cnt = min(32, end - base);

#pragma unroll 8
        for (int j = 0; j < cnt; j++) {
            int   cj = __shfl_sync(0xffffffffu, col, j);
            float vj = __shfl_sync(0xffffffffu, v,   j);
            uint2 hraw = *reinterpret_cast<const uint2*>(
                             Hbase + (size_t)cj * OUTC + lane * 4);
            __half2 h0 = *reinterpret_cast<__half2*>(&hraw.x);
            __half2 h1 = *reinterpret_cast<__half2*>(&hraw.y);
            float2 f0 = __half22float2(h0);
            float2 f1 = __half22float2(h1);
            acc.x = fmaf(vj, f0.x, acc.x);
            acc.y = fmaf(vj, f0.y, acc.y);
            acc.z = fmaf(vj, f1.x, acc.z);
            acc.w = fmaf(vj, f1.y, acc.w);
        }
    }

    *reinterpret_cast<float4*>(out + (size_t)r * OUTC + lane * 4) = acc;
}

// ---------------------------------------------------------------------------
extern "C" void kernel_launch(void* const* d_in, const int* in_sizes, int n_in,
                              void* d_out, int out_size)
{
    const float* X      = (const float*)d_in[0];   // [NN, INC]
    const float* W      = (const float*)d_in[1];   // [OUTC, INC]
    const int*   A_rows = (const int*)  d_in[2];   // [EE] sorted
    const int*   A_cols = (const int*)  d_in[3];   // [EE]
    const float* A_vals = (const float*)d_in[4];   // [EE]
    float*       out    = (float*)d_out;           // [NN, OUTC]

    cudaFuncSetAttribute(gemm_tc_kernel,
                         cudaFuncAttributeMaxDynamicSharedMemorySize, SM_BYTES);

    prep_kernel<<<(EE / 4 + 255) / 256, 256>>>(W, A_rows);
    gemm_tc_kernel<<<(NN + 127) / 128, 256, SM_BYTES>>>(X);
    spmm_kernel<<<(NN + 7) / 8, 256>>>(A_cols, A_vals, out);
}